// round 16
// baseline (speedup 1.0000x reference)
#include <cuda_runtime.h>
#include <cuda_bf16.h>
#include <mma.h>
#include <math.h>
#include <float.h>
#include <stdint.h>

using namespace nvcuda;

#define BB   32
#define SS   4096
#define INF_ 256
#define DD   64
#define KK   8
#define NROW (BB*SS)          // 131072
#define EPSN 1e-5f
#define CS   128              // S-chunk for fused iteration kernel (R13 proven)
#define NCH  (SS/CS)          // 32

typedef unsigned long long ULL;

// ---------------- packed fp32x2 helpers (FFMA2 path) ----------------
__device__ __forceinline__ ULL pk2(float lo, float hi) {
    ULL r; asm("mov.b64 %0, {%1, %2};" : "=l"(r) : "f"(lo), "f"(hi)); return r;
}
__device__ __forceinline__ void fma2(ULL& d, ULL a, ULL b) {
    asm("fma.rn.f32x2 %0, %1, %2, %0;" : "+l"(d) : "l"(a), "l"(b));
}
__device__ __forceinline__ float2 upk2(ULL v) {
    float2 f; asm("mov.b64 {%0, %1}, %2;" : "=f"(f.x), "=f"(f.y) : "l"(v)); return f;
}

// ---------------- scratch (device globals; no allocation allowed) ----------------
__device__ __align__(16) float g_k[NROW*DD];             // 33.5 MB
__device__ __align__(16) float g_v[NROW*DD];             // 33.5 MB
__device__ __align__(16) float g_q[BB*KK*DD];
__device__ __align__(16) float g_slots[BB*KK*DD];
__device__ __align__(16) float g_updp[NCH*BB*KK*DD];
__device__ float g_cst[NCH*BB*KK*2];
__device__ float g_stats[BB*KK*2];
__device__ float g_cb[2*DD];                             // b_ln @ [Wk|Wv] (exact fp32)
__device__ float g_wsum[2*DD];                           // colsum of g-folded weights
__device__ __align__(16) __nv_bfloat16 g_whT[128*INF_];  // split weights, transposed [n][k]
__device__ __align__(16) __nv_bfloat16 g_wlT[128*INF_];

// ---------------- init: slots broadcast + bias/colsum precompute ----------------
__global__ void k_init(const float* __restrict__ slot_emb,
                       const float* __restrict__ Wk, const float* __restrict__ Wv,
                       const float* __restrict__ lnb, const float* __restrict__ gln) {
    int t = blockIdx.x*blockDim.x + threadIdx.x;
    if (t < BB*KK*DD) g_slots[t] = slot_emb[t % (KK*DD)];
    if (t < 2*DD) {
        float s = 0.f, sw = 0.f;
        for (int i = 0; i < INF_; i++) {
            float w = (t < DD) ? Wk[i*DD + t] : Wv[i*DD + (t-DD)];
            s  += lnb[i]*w;
            sw += gln[i]*w;
        }
        g_cb[t]   = s;
        g_wsum[t] = sw;
    }
}

// ---------------- weight split: [k][n] fp32 -> transposed bf16 hi/lo [n][k] ------
__global__ void k_wsplit(const float* __restrict__ Wk, const float* __restrict__ Wv,
                         const float* __restrict__ gln) {
    int idx = blockIdx.x*256 + threadIdx.x;     // over 128 n x 256 k
    int n = idx >> 8, k = idx & 255;
    float w = gln[k] * ((n < DD) ? Wk[k*DD + n] : Wv[k*DD + (n - DD)]);
    __nv_bfloat16 hi = __float2bfloat16(w);
    __nv_bfloat16 lo = __float2bfloat16(w - __bfloat162float(hi));
    g_whT[n*INF_ + k] = hi;
    g_wlT[n*INF_ + k] = lo;
}

// ---------------- phase 1: K/V projection on RAW x via wmma bf16 2-split ---------
// LN folded into the epilogue: y = rr*(x@Wg) - rr*m*S + cb  (row affine).
// x read EXACTLY once; row stats accumulated during staging.
#define LDP 40
#define SMB (128*LDP*2)       // one bf16 tile = 10240 B

__global__ __launch_bounds__(256, 2) void k_proj(const float* __restrict__ x) {
    __shared__ __align__(16) char smbuf[4*SMB];          // A/B tiles; reused as epilogue buf
    __shared__ float ssum[256], ssum2[256];
    __shared__ float sa[128], sb2[128];                  // rr, rr*m
    __shared__ float scb[128], sws[128];

    __nv_bfloat16 (*Ah)[LDP] = (__nv_bfloat16(*)[LDP])(smbuf);
    __nv_bfloat16 (*Al)[LDP] = (__nv_bfloat16(*)[LDP])(smbuf + SMB);
    __nv_bfloat16 (*Bh)[LDP] = (__nv_bfloat16(*)[LDP])(smbuf + 2*SMB);
    __nv_bfloat16 (*Bl)[LDP] = (__nv_bfloat16(*)[LDP])(smbuf + 3*SMB);
    float (*es)[132] = (float(*)[132])(smbuf);           // 64 x 132 fp32 = 33792 B

    int tid = threadIdx.x, wid = tid >> 5;
    int row0 = blockIdx.x * 128;
    int wm = wid & 3;
    int wn = wid >> 2;

    wmma::fragment<wmma::accumulator, 16, 16, 16, float> acc[2][4];
    #pragma unroll
    for (int mt = 0; mt < 2; mt++)
        #pragma unroll
        for (int nt = 0; nt < 4; nt++) wmma::fill_fragment(acc[mt][nt], 0.f);

    int r_  = tid >> 1;          // staging row (A) / n (B)
    int kh  = (tid & 1) * 16;    // k half within chunk
    float s_loc = 0.f, s2_loc = 0.f;

    for (int c = 0; c < 8; c++) {
        __syncthreads();
        // ---- stage A: raw x 128x32 chunk, bf16 hi/lo split + running stats ----
        {
            const float* xp = x + (size_t)(row0 + r_)*INF_ + c*32 + kh;
            float4 v0 = *(const float4*)xp;
            float4 v1 = *(const float4*)(xp + 4);
            float4 v2 = *(const float4*)(xp + 8);
            float4 v3 = *(const float4*)(xp + 12);
            float vv[16] = {v0.x,v0.y,v0.z,v0.w, v1.x,v1.y,v1.z,v1.w,
                            v2.x,v2.y,v2.z,v2.w, v3.x,v3.y,v3.z,v3.w};
            uint32_t hw[8], lw[8];
            #pragma unroll
            for (int p = 0; p < 8; p++) {
                float a0 = vv[2*p], a1 = vv[2*p+1];
                s_loc  += a0 + a1;
                s2_loc += a0*a0 + a1*a1;
                __nv_bfloat16 h0 = __float2bfloat16(a0);
                __nv_bfloat16 h1 = __float2bfloat16(a1);
                __nv_bfloat162 hp(h0, h1);
                __nv_bfloat162 lp = __floats2bfloat162_rn(a0 - __bfloat162float(h0),
                                                          a1 - __bfloat162float(h1));
                hw[p] = *(uint32_t*)&hp;
                lw[p] = *(uint32_t*)&lp;
            }
            *(uint4*)&Ah[r_][kh]     = make_uint4(hw[0],hw[1],hw[2],hw[3]);
            *(uint4*)&Ah[r_][kh + 8] = make_uint4(hw[4],hw[5],hw[6],hw[7]);
            *(uint4*)&Al[r_][kh]     = make_uint4(lw[0],lw[1],lw[2],lw[3]);
            *(uint4*)&Al[r_][kh + 8] = make_uint4(lw[4],lw[5],lw[6],lw[7]);
        }
        // ---- stage B: split weights [n][k] ----
        {
            const __nv_bfloat16* wh = g_whT + r_*INF_ + c*32 + kh;
            const __nv_bfloat16* wl = g_wlT + r_*INF_ + c*32 + kh;
            uint4 h0 = *(const uint4*)wh, h1 = *(const uint4*)(wh + 8);
            uint4 l0 = *(const uint4*)wl, l1 = *(const uint4*)(wl + 8);
            *(uint4*)&Bh[r_][kh]     = h0;
            *(uint4*)&Bh[r_][kh + 8] = h1;
            *(uint4*)&Bl[r_][kh]     = l0;
            *(uint4*)&Bl[r_][kh + 8] = l1;
        }
        __syncthreads();

        #pragma unroll
        for (int ks = 0; ks < 2; ks++) {
            wmma::fragment<wmma::matrix_a, 16,16,16, __nv_bfloat16, wmma::row_major> ah[2], al[2];
            #pragma unroll
            for (int mt = 0; mt < 2; mt++) {
                wmma::load_matrix_sync(ah[mt], &Ah[wm*32 + mt*16][ks*16], LDP);
                wmma::load_matrix_sync(al[mt], &Al[wm*32 + mt*16][ks*16], LDP);
            }
            #pragma unroll
            for (int nt = 0; nt < 4; nt++) {
                wmma::fragment<wmma::matrix_b, 16,16,16, __nv_bfloat16, wmma::col_major> bh, bl;
                wmma::load_matrix_sync(bh, &Bh[wn*64 + nt*16][ks*16], LDP);
                wmma::load_matrix_sync(bl, &Bl[wn*64 + nt*16][ks*16], LDP);
                #pragma unroll
                for (int mt = 0; mt < 2; mt++) {
                    wmma::mma_sync(acc[mt][nt], ah[mt], bh, acc[mt][nt]);
                    wmma::mma_sync(acc[mt][nt], ah[mt], bl, acc[mt][nt]);
                    wmma::mma_sync(acc[mt][nt], al[mt], bh, acc[mt][nt]);
                }
            }
        }
    }

    // ---- row stats combine (2 threads per row, fixed order) ----
    ssum[tid] = s_loc; ssum2[tid] = s2_loc;
    __syncthreads();
    if (tid < 128) {
        float s  = ssum[2*tid]  + ssum[2*tid + 1];
        float s2 = ssum2[2*tid] + ssum2[2*tid + 1];
        float m  = s * (1.f/INF_);
        float rr = rsqrtf(s2*(1.f/INF_) - m*m + EPSN);
        sa[tid]  = rr;
        sb2[tid] = rr*m;
        scb[tid] = g_cb[tid];
        sws[tid] = g_wsum[tid];
    }

    // ---- epilogue in two halves: fragments -> SMEM -> row-affine -> gmem ----
    #pragma unroll
    for (int mt = 0; mt < 2; mt++) {
        __syncthreads();
        #pragma unroll
        for (int nt = 0; nt < 4; nt++)
            wmma::store_matrix_sync(&es[wm*16][wn*64 + nt*16], acc[mt][nt], 132,
                                    wmma::mem_row_major);
        __syncthreads();
        #pragma unroll
        for (int j = 0; j < 8; j++) {
            int f  = tid + j*256;            // 0..2047 float4 slots (64 x 32)
            int rl = f >> 5, c4 = (f & 31)*4;
            int gl = ((rl >> 4) << 5) + mt*16 + (rl & 15);   // local row 0..127
            float a = sa[gl], b2 = sb2[gl];
            float4 vv = *(const float4*)&es[rl][c4];
            float o0 = a*vv.x - b2*sws[c4]   + scb[c4];
            float o1 = a*vv.y - b2*sws[c4+1] + scb[c4+1];
            float o2 = a*vv.z - b2*sws[c4+2] + scb[c4+2];
            float o3 = a*vv.w - b2*sws[c4+3] + scb[c4+3];
            int grow = row0 + gl;
            if (c4 < DD)
                *(float4*)&g_k[(size_t)grow*DD + c4] = make_float4(o0,o1,o2,o3);
            else
                *(float4*)&g_v[(size_t)grow*DD + (c4 - DD)] = make_float4(o0,o1,o2,o3);
        }
    }
}

// ---------------- slot LN + q projection (standalone, used once) ----------------
__global__ void k_q(const float* __restrict__ Wq, const float* __restrict__ g,
                    const float* __restrict__ bb) {
    int row = blockIdx.x, d = threadIdx.x;   // 64 threads
    __shared__ float sn[64];
    __shared__ float red[2];
    float xv = g_slots[row*DD + d];
    int lane = d & 31, w = d >> 5;
    float s = xv;
    #pragma unroll
    for (int o = 16; o; o >>= 1) s += __shfl_xor_sync(0xffffffffu, s, o);
    if (lane == 0) red[w] = s;
    __syncthreads();
    float m = (red[0] + red[1]) * (1.f/DD);
    __syncthreads();
    float df = xv - m;
    float q2 = df*df;
    #pragma unroll
    for (int o = 16; o; o >>= 1) q2 += __shfl_xor_sync(0xffffffffu, q2, o);
    if (lane == 0) red[w] = q2;
    __syncthreads();
    float var = (red[0] + red[1]) * (1.f/DD);
    float rs = rsqrtf(var + EPSN);
    sn[d] = df*rs*g[d] + bb[d];
    __syncthreads();
    float acc = 0.f;
    #pragma unroll 8
    for (int j = 0; j < DD; j++) acc += sn[j]*Wq[j*DD + d];
    g_q[row*DD + d] = acc;
}

// ---------------- fused iteration (R13 version: CS=128) ----------------
__global__ __launch_bounds__(256) void k_iter(const int* __restrict__ mask,
                                              float* __restrict__ attn, int last) {
    __shared__ float  qs[KK][64];
    __shared__ float  ks[CS][68];
    __shared__ float  ps[KK][CS];
    __shared__ __align__(16) float2 psd[CS][KK];
    int b = blockIdx.y, ch = blockIdx.x, s0 = ch*CS;
    int tid = threadIdx.x, lane = tid & 31, w = tid >> 5;

    ((float2*)qs)[tid] = ((const float2*)(g_q + b*KK*DD))[tid];
    #pragma unroll
    for (int it = 0; it < 8; it++) {
        int f = tid + it*256;
        int r = f >> 4, c = (f & 15)*4;
        float4 kv = *(const float4*)&g_k[((size_t)(b*SS + s0 + r))*DD + c];
        *(float4*)&ks[r][c] = kv;
    }
    __syncthreads();

    {
        int r = tid & 127, h = tid >> 7;
        ULL acc[4] = {0ull,0ull,0ull,0ull};
        #pragma unroll
        for (int i = 0; i < 16; i++) {
            ulonglong2 kv = *(const ulonglong2*)&ks[r][i*4];
            #pragma unroll
            for (int sg = 0; sg < 4; sg++) {
                ulonglong2 qp = *(const ulonglong2*)&qs[h*4 + sg][i*4];
                fma2(acc[sg], qp.x, kv.x);
                fma2(acc[sg], qp.y, kv.y);
            }
        }
        int mk = mask[b*SS + s0 + r];
        #pragma unroll
        for (int sg = 0; sg < 4; sg++) {
            float2 t = upk2(acc[sg]);
            float sc = (t.x + t.y)*0.125f;
            if (mk == 0) sc = -3.402823466e38f;
            ps[h*4 + sg][r] = sc;
            if (last) attn[((size_t)(b*KK + h*4 + sg))*SS + s0 + r] = sc;
        }
    }
    __syncthreads();

    {
        float m = -FLT_MAX;
        #pragma unroll
        for (int j = 0; j < CS/32; j++) m = fmaxf(m, ps[w][lane + 32*j]);
        #pragma unroll
        for (int o = 16; o; o >>= 1) m = fmaxf(m, __shfl_xor_sync(0xffffffffu, m, o));
        float l = 0.f;
        #pragma unroll
        for (int j = 0; j < CS/32; j++) {
            float p = expf(ps[w][lane + 32*j] - m);
            psd[lane + 32*j][w] = make_float2(p, p);
            l += p;
        }
        #pragma unroll
        for (int o = 16; o; o >>= 1) l += __shfl_xor_sync(0xffffffffu, l, o);
        if (lane == 0) {
            g_cst[((ch*BB + b)*KK + w)*2]     = m;
            g_cst[((ch*BB + b)*KK + w)*2 + 1] = l;
        }
    }
    __syncthreads();

    {
        const float* vp = g_v + ((size_t)(b*SS + s0 + w*16))*DD + 2*lane;
        ULL acc[8];
        #pragma unroll
        for (int sl = 0; sl < 8; sl++) acc[sl] = 0ull;
        #pragma unroll
        for (int s = 0; s < 16; s++) {
            ULL vv = *(const ULL*)(vp + (size_t)s*DD);
            const ulonglong2* pp = (const ulonglong2*)&psd[w*16 + s][0];
            ulonglong2 pA = pp[0], pB = pp[1], pC = pp[2], pD = pp[3];
            fma2(acc[0], pA.x, vv); fma2(acc[1], pA.y, vv);
            fma2(acc[2], pB.x, vv); fma2(acc[3], pB.y, vv);
            fma2(acc[4], pC.x, vv); fma2(acc[5], pC.y, vv);
            fma2(acc[6], pD.x, vv); fma2(acc[7], pD.y, vv);
        }
        float* pt = &ks[0][0];
        #pragma unroll
        for (int sl = 0; sl < 8; sl++)
            *(float2*)&pt[(w*8 + sl)*64 + 2*lane] = upk2(acc[sl]);
    }
    __syncthreads();

    {
        int sl = tid >> 5, dp = lane;
        const float* pt = &ks[0][0];
        float sx = 0.f, sy = 0.f;
        #pragma unroll
        for (int ww = 0; ww < 8; ww++) {
            float2 p = *(const float2*)&pt[(ww*8 + sl)*64 + 2*dp];
            sx += p.x; sy += p.y;
        }
        *(float2*)&g_updp[((size_t)(ch*BB + b)*KK + sl)*DD + 2*dp] = make_float2(sx, sy);
    }
}

// ---------------- GRU cell + fused next-iteration q projection (clean) ----------
__global__ __launch_bounds__(192) void k_gru(const float* __restrict__ W_ih,
                                             const float* __restrict__ W_hh,
                                             const float* __restrict__ b_ih,
                                             const float* __restrict__ b_hh,
                                             const float* __restrict__ Wq,
                                             const float* __restrict__ lng,
                                             const float* __restrict__ lnb) {
    __shared__ float su[64], sh[64], gx[192], gh[192], red[2];
    int row = blockIdx.x, tid = threadIdx.x;   // row = b*KK + slot
    int lane = tid & 31, w = tid >> 5;
    if (tid < 64) {
        float m = -FLT_MAX;
        #pragma unroll
        for (int ch = 0; ch < NCH; ch++)
            m = fmaxf(m, g_cst[(ch*BB*KK + row)*2]);
        float l = 0.f, U = 0.f;
        #pragma unroll
        for (int ch = 0; ch < NCH; ch++) {
            float wgt = expf(g_cst[(ch*BB*KK + row)*2] - m);
            l += g_cst[(ch*BB*KK + row)*2 + 1] * wgt;
            U += g_updp[((size_t)ch*BB*KK + row)*DD + tid] * wgt;
        }
        su[tid] = U / l;
        sh[tid] = g_slots[row*DD + tid];
        if (tid == 0) { g_stats[row*2] = m; g_stats[row*2+1] = 1.f/l; }
    }
    __syncthreads();
    float ax = b_ih[tid], ah = b_hh[tid];
    #pragma unroll 8
    for (int j = 0; j < 64; j++) {
        ax += su[j]*W_ih[j*192 + tid];
        ah += sh[j]*W_hh[j*192 + tid];
    }
    gx[tid] = ax; gh[tid] = ah;
    __syncthreads();
    float ns = 0.f;
    if (tid < 64) {
        float r = 1.f/(1.f + expf(-(gx[tid]      + gh[tid])));
        float z = 1.f/(1.f + expf(-(gx[tid+64]   + gh[tid+64])));
        float n = tanhf(gx[tid+128] + r*gh[tid+128]);
        ns = (1.f - z)*n + z*sh[tid];
        g_slots[row*DD + tid] = ns;
    }
    __syncthreads();
    // ---- fused q projection for the NEXT iteration (LN + matvec, k_q pattern) ----
    if (tid < 64) {
        float s = ns;
        #pragma unroll
        for (int o = 16; o; o >>= 1) s += __shfl_xor_sync(0xffffffffu, s, o);
        if (lane == 0) red[w] = s;
    }
    __syncthreads();
    float m_ = (red[0] + red[1]) * (1.f/DD);
    float df = ns - m_;
    __syncthreads();
    if (tid < 64) {
        float q2 = df*df;
        #pragma unroll
        for (int o = 16; o; o >>= 1) q2 += __shfl_xor_sync(0xffffffffu, q2, o);
        if (lane == 0) red[w] = q2;
    }
    __syncthreads();
    if (tid < 64) {
        float var = (red[0] + red[1]) * (1.f/DD);
        float rs = rsqrtf(var + EPSN);
        sh[tid] = df*rs*lng[tid] + lnb[tid];
    }
    __syncthreads();
    if (tid < 64) {
        float acc = 0.f;
        #pragma unroll 8
        for (int j = 0; j < DD; j++) acc += sh[j]*Wq[j*DD + tid];
        g_q[row*DD + tid] = acc;
    }
}

// ---------------- normalize raw scores into attn probabilities ----------------
__global__ __launch_bounds__(256) void k_attn(float* __restrict__ attn) {
    int row = blockIdx.x;
    float m  = g_stats[row*2];
    float rl = g_stats[row*2 + 1];
    float* a = attn + (size_t)row*SS;
    for (int i = threadIdx.x; i < SS; i += 256)
        a[i] = expf(a[i] - m) * rl;
}

// ---------------- final: write slots + validity mask ----------------
__global__ void k_final(const float* __restrict__ Wval, const float* __restrict__ bval,
                        float* __restrict__ out) {
    int row = blockIdx.x, d = threadIdx.x;
    __shared__ float red[2];
    float s = g_slots[row*DD + d];
    out[row*DD + d] = s;
    float p = s*Wval[d];
    int lane = d & 31, w = d >> 5;
    #pragma unroll
    for (int o = 16; o; o >>= 1) p += __shfl_xor_sync(0xffffffffu, p, o);
    if (lane == 0) red[w] = p;
    __syncthreads();
    if (d == 0) {
        float v = red[0] + red[1] + bval[0];
        out[(size_t)BB*KK*DD + (size_t)BB*KK*SS + row] = (v > 0.f) ? 1.f : 0.f;
    }
}

// ---------------- launch ----------------
extern "C" void kernel_launch(void* const* d_in, const int* in_sizes, int n_in,
                              void* d_out, int out_size) {
    const float* inputs   = (const float*)d_in[0];
    const int*   mask     = (const int*)  d_in[1];
    const float* slot_emb = (const float*)d_in[2];
    const float* Wq       = (const float*)d_in[3];
    const float* Wk       = (const float*)d_in[4];
    const float* Wv       = (const float*)d_in[5];
    const float* W_ih     = (const float*)d_in[6];
    const float* W_hh     = (const float*)d_in[7];
    const float* b_ih     = (const float*)d_in[8];
    const float* b_hh     = (const float*)d_in[9];
    const float* ln_in_g  = (const float*)d_in[10];
    const float* ln_in_b  = (const float*)d_in[11];
    const float* ln_s_g   = (const float*)d_in[12];
    const float* ln_s_b   = (const float*)d_in[13];
    const float* Wval     = (const float*)d_in[14];
    const float* bval     = (const float*)d_in[15];
    float* out  = (float*)d_out;
    float* attn = out + BB*KK*DD;   // attn region of d_out doubles as raw-score scratch

    k_init<<<64, 256>>>(slot_emb, Wk, Wv, ln_in_b, ln_in_g);
    k_wsplit<<<128, 256>>>(Wk, Wv, ln_in_g);
    k_proj<<<NROW/128, 256>>>(inputs);
    k_q<<<BB*KK, 64>>>(Wq, ln_s_g, ln_s_b);
    for (int it = 0; it < 3; it++) {
        k_iter<<<dim3(NCH, BB), 256>>>(mask, attn, (it == 2) ? 1 : 0);
        k_gru<<<BB*KK, 192>>>(W_ih, W_hh, b_ih, b_hh, Wq, ln_s_g, ln_s_b);
    }
    k_attn<<<BB*KK, 256>>>(attn);
    k_final<<<BB*KK, 64>>>(Wval, bval, out);
}

// round 17
// speedup vs baseline: 1.3798x; 1.3798x over previous
#include <cuda_runtime.h>
#include <cuda_bf16.h>
#include <mma.h>
#include <math.h>
#include <float.h>
#include <stdint.h>

using namespace nvcuda;

#define BB   32
#define SS   4096
#define INF_ 256
#define DD   64
#define KK   8
#define NROW (BB*SS)          // 131072
#define EPSN 1e-5f
#define CS   128              // S-chunk for fused iteration kernel (R13 proven)
#define NCH  (SS/CS)          // 32

typedef unsigned long long ULL;

// ---------------- packed fp32x2 helpers (FFMA2 path) ----------------
__device__ __forceinline__ ULL pk2(float lo, float hi) {
    ULL r; asm("mov.b64 %0, {%1, %2};" : "=l"(r) : "f"(lo), "f"(hi)); return r;
}
__device__ __forceinline__ void fma2(ULL& d, ULL a, ULL b) {
    asm("fma.rn.f32x2 %0, %1, %2, %0;" : "+l"(d) : "l"(a), "l"(b));
}
__device__ __forceinline__ float2 upk2(ULL v) {
    float2 f; asm("mov.b64 {%0, %1}, %2;" : "=f"(f.x), "=f"(f.y) : "l"(v)); return f;
}

// ---------------- scratch (device globals; no allocation allowed) ----------------
__device__ __align__(16) float g_k[NROW*DD];             // 33.5 MB
__device__ __align__(16) float g_v[NROW*DD];             // 33.5 MB
__device__ __align__(16) float g_q[BB*KK*DD];
__device__ __align__(16) float g_slots[BB*KK*DD];
__device__ __align__(16) float g_updp[NCH*BB*KK*DD];
__device__ float g_cst[NCH*BB*KK*2];
__device__ float g_stats[BB*KK*2];
__device__ float g_cb[2*DD];                             // b_ln @ [Wk|Wv] (exact fp32)
__device__ __align__(16) __nv_bfloat16 g_whT[128*INF_];  // split weights, transposed [n][k]
__device__ __align__(16) __nv_bfloat16 g_wlT[128*INF_];

// ---------------- init: slots broadcast + epilogue bias precompute ----------------
__global__ void k_init(const float* __restrict__ slot_emb,
                       const float* __restrict__ Wk, const float* __restrict__ Wv,
                       const float* __restrict__ lnb) {
    int t = blockIdx.x*blockDim.x + threadIdx.x;
    if (t < BB*KK*DD) g_slots[t] = slot_emb[t % (KK*DD)];
    if (t < 2*DD) {
        float s = 0.f;
        for (int i = 0; i < INF_; i++) {
            float w = (t < DD) ? Wk[i*DD + t] : Wv[i*DD + (t-DD)];
            s += lnb[i]*w;
        }
        g_cb[t] = s;
    }
}

// ---------------- weight split: [k][n] fp32 -> transposed bf16 hi/lo [n][k] ------
__global__ void k_wsplit(const float* __restrict__ Wk, const float* __restrict__ Wv,
                         const float* __restrict__ gln) {
    int idx = blockIdx.x*256 + threadIdx.x;     // over 128 n x 256 k
    int n = idx >> 8, k = idx & 255;
    float w = gln[k] * ((n < DD) ? Wk[k*DD + n] : Wv[k*DD + (n - DD)]);
    __nv_bfloat16 hi = __float2bfloat16(w);
    __nv_bfloat16 lo = __float2bfloat16(w - __bfloat162float(hi));
    g_whT[n*INF_ + k] = hi;
    g_wlT[n*INF_ + k] = lo;
}

// ---------------- phase 1: fused LN + K/V projection via wmma bf16 2-split -------
// (EXACT R13 version — proven 260.9 µs baseline component; do not touch)
#define LDP 40

__global__ __launch_bounds__(256, 2) void k_proj(const float* __restrict__ x) {
    __shared__ __align__(16) __nv_bfloat16 Ah[128][LDP];
    __shared__ __align__(16) __nv_bfloat16 Al[128][LDP];
    __shared__ __align__(16) __nv_bfloat16 Bh[128][LDP];
    __shared__ __align__(16) __nv_bfloat16 Bl[128][LDP];
    __shared__ float rm[128], rr[128], scb[128];

    int tid = threadIdx.x, wid = tid >> 5, lane = tid & 31;
    int row0 = blockIdx.x * 128;
    int wm = wid & 3;
    int wn = wid >> 2;

    for (int j = 0; j < 16; j++) {
        int r = wid*16 + j;
        const float* xr = x + (size_t)(row0 + r)*INF_;
        float s = 0.f, s2 = 0.f;
        for (int i = lane; i < INF_; i += 32) { float v = xr[i]; s += v; s2 += v*v; }
        #pragma unroll
        for (int o = 16; o; o >>= 1) {
            s  += __shfl_xor_sync(0xffffffffu, s,  o);
            s2 += __shfl_xor_sync(0xffffffffu, s2, o);
        }
        if (lane == 0) {
            float m = s * (1.f/INF_);
            rm[r] = m;
            rr[r] = rsqrtf(s2*(1.f/INF_) - m*m + EPSN);
        }
    }
    if (tid < 128) scb[tid] = g_cb[tid];

    wmma::fragment<wmma::accumulator, 16, 16, 16, float> acc[2][4];
    #pragma unroll
    for (int mt = 0; mt < 2; mt++)
        #pragma unroll
        for (int nt = 0; nt < 4; nt++) wmma::fill_fragment(acc[mt][nt], 0.f);

    int r_  = tid >> 1;
    int kh  = (tid & 1) * 16;

    for (int c = 0; c < 8; c++) {
        __syncthreads();
        {
            float m = rm[r_], rs = rr[r_];
            const float* xp = x + (size_t)(row0 + r_)*INF_ + c*32 + kh;
            float4 v0 = *(const float4*)xp;
            float4 v1 = *(const float4*)(xp + 4);
            float4 v2 = *(const float4*)(xp + 8);
            float4 v3 = *(const float4*)(xp + 12);
            float vv[16] = {v0.x,v0.y,v0.z,v0.w, v1.x,v1.y,v1.z,v1.w,
                            v2.x,v2.y,v2.z,v2.w, v3.x,v3.y,v3.z,v3.w};
            uint32_t hw[8], lw[8];
            #pragma unroll
            for (int p = 0; p < 8; p++) {
                float a0 = (vv[2*p]   - m)*rs;
                float a1 = (vv[2*p+1] - m)*rs;
                __nv_bfloat16 h0 = __float2bfloat16(a0);
                __nv_bfloat16 h1 = __float2bfloat16(a1);
                __nv_bfloat162 hp(h0, h1);
                __nv_bfloat162 lp = __floats2bfloat162_rn(a0 - __bfloat162float(h0),
                                                          a1 - __bfloat162float(h1));
                hw[p] = *(uint32_t*)&hp;
                lw[p] = *(uint32_t*)&lp;
            }
            *(uint4*)&Ah[r_][kh]     = make_uint4(hw[0],hw[1],hw[2],hw[3]);
            *(uint4*)&Ah[r_][kh + 8] = make_uint4(hw[4],hw[5],hw[6],hw[7]);
            *(uint4*)&Al[r_][kh]     = make_uint4(lw[0],lw[1],lw[2],lw[3]);
            *(uint4*)&Al[r_][kh + 8] = make_uint4(lw[4],lw[5],lw[6],lw[7]);
        }
        {
            const __nv_bfloat16* wh = g_whT + r_*INF_ + c*32 + kh;
            const __nv_bfloat16* wl = g_wlT + r_*INF_ + c*32 + kh;
            uint4 h0 = *(const uint4*)wh, h1 = *(const uint4*)(wh + 8);
            uint4 l0 = *(const uint4*)wl, l1 = *(const uint4*)(wl + 8);
            *(uint4*)&Bh[r_][kh]     = h0;
            *(uint4*)&Bh[r_][kh + 8] = h1;
            *(uint4*)&Bl[r_][kh]     = l0;
            *(uint4*)&Bl[r_][kh + 8] = l1;
        }
        __syncthreads();

        #pragma unroll
        for (int ks = 0; ks < 2; ks++) {
            wmma::fragment<wmma::matrix_a, 16,16,16, __nv_bfloat16, wmma::row_major> ah[2], al[2];
            #pragma unroll
            for (int mt = 0; mt < 2; mt++) {
                wmma::load_matrix_sync(ah[mt], &Ah[wm*32 + mt*16][ks*16], LDP);
                wmma::load_matrix_sync(al[mt], &Al[wm*32 + mt*16][ks*16], LDP);
            }
            #pragma unroll
            for (int nt = 0; nt < 4; nt++) {
                wmma::fragment<wmma::matrix_b, 16,16,16, __nv_bfloat16, wmma::col_major> bh, bl;
                wmma::load_matrix_sync(bh, &Bh[wn*64 + nt*16][ks*16], LDP);
                wmma::load_matrix_sync(bl, &Bl[wn*64 + nt*16][ks*16], LDP);
                #pragma unroll
                for (int mt = 0; mt < 2; mt++) {
                    wmma::mma_sync(acc[mt][nt], ah[mt], bh, acc[mt][nt]);
                    wmma::mma_sync(acc[mt][nt], ah[mt], bl, acc[mt][nt]);
                    wmma::mma_sync(acc[mt][nt], al[mt], bh, acc[mt][nt]);
                }
            }
        }
    }

    __syncthreads();
    {
        __nv_bfloat16 one = __float2bfloat16(1.f);
        float cbv = scb[r_];
        __nv_bfloat16 ch = __float2bfloat16(cbv);
        __nv_bfloat16 cl = __float2bfloat16(cbv - __bfloat162float(ch));
        #pragma unroll
        for (int j = 0; j < 16; j++) {
            int kcol = kh + j;
            Ah[r_][kcol] = (kcol == 0) ? one : __float2bfloat16(0.f);
            Bh[r_][kcol] = (kcol == 0) ? ch  : __float2bfloat16(0.f);
            Bl[r_][kcol] = (kcol == 0) ? cl  : __float2bfloat16(0.f);
        }
    }
    __syncthreads();
    {
        wmma::fragment<wmma::matrix_a, 16,16,16, __nv_bfloat16, wmma::row_major> ah[2];
        #pragma unroll
        for (int mt = 0; mt < 2; mt++)
            wmma::load_matrix_sync(ah[mt], &Ah[wm*32 + mt*16][0], LDP);
        #pragma unroll
        for (int nt = 0; nt < 4; nt++) {
            wmma::fragment<wmma::matrix_b, 16,16,16, __nv_bfloat16, wmma::col_major> bh, bl;
            wmma::load_matrix_sync(bh, &Bh[wn*64 + nt*16][0], LDP);
            wmma::load_matrix_sync(bl, &Bl[wn*64 + nt*16][0], LDP);
            #pragma unroll
            for (int mt = 0; mt < 2; mt++) {
                wmma::mma_sync(acc[mt][nt], ah[mt], bh, acc[mt][nt]);
                wmma::mma_sync(acc[mt][nt], ah[mt], bl, acc[mt][nt]);
            }
        }
    }

    #pragma unroll
    for (int mt = 0; mt < 2; mt++) {
        int rb = row0 + wm*32 + mt*16;
        #pragma unroll
        for (int nt = 0; nt < 4; nt++) {
            int n = wn*64 + nt*16;
            float* dst = (n < DD) ? &g_k[(size_t)rb*DD + n]
                                  : &g_v[(size_t)rb*DD + (n - DD)];
            wmma::store_matrix_sync(dst, acc[mt][nt], DD, wmma::mem_row_major);
        }
    }
}

// ---------------- slot LN + q projection (standalone; runs ONCE for initial slots) --
__global__ void k_q(const float* __restrict__ Wq, const float* __restrict__ g,
                    const float* __restrict__ bb) {
    int row = blockIdx.x, d = threadIdx.x;   // 64 threads
    __shared__ float sn[64];
    __shared__ float red[2];
    float xv = g_slots[row*DD + d];
    int lane = d & 31, w = d >> 5;
    float s = xv;
    #pragma unroll
    for (int o = 16; o; o >>= 1) s += __shfl_xor_sync(0xffffffffu, s, o);
    if (lane == 0) red[w] = s;
    __syncthreads();
    float m = (red[0] + red[1]) * (1.f/DD);
    __syncthreads();
    float df = xv - m;
    float q2 = df*df;
    #pragma unroll
    for (int o = 16; o; o >>= 1) q2 += __shfl_xor_sync(0xffffffffu, q2, o);
    if (lane == 0) red[w] = q2;
    __syncthreads();
    float var = (red[0] + red[1]) * (1.f/DD);
    float rs = rsqrtf(var + EPSN);
    sn[d] = df*rs*g[d] + bb[d];
    __syncthreads();
    float acc = 0.f;
    #pragma unroll 8
    for (int j = 0; j < DD; j++) acc += sn[j]*Wq[j*DD + d];
    g_q[row*DD + d] = acc;
}

// ---------------- fused iteration (EXACT R13 version: CS=128) ----------------
__global__ __launch_bounds__(256) void k_iter(const int* __restrict__ mask,
                                              float* __restrict__ attn, int last) {
    __shared__ float  qs[KK][64];
    __shared__ float  ks[CS][68];
    __shared__ float  ps[KK][CS];
    __shared__ __align__(16) float2 psd[CS][KK];
    int b = blockIdx.y, ch = blockIdx.x, s0 = ch*CS;
    int tid = threadIdx.x, lane = tid & 31, w = tid >> 5;

    ((float2*)qs)[tid] = ((const float2*)(g_q + b*KK*DD))[tid];
    #pragma unroll
    for (int it = 0; it < 8; it++) {
        int f = tid + it*256;
        int r = f >> 4, c = (f & 15)*4;
        float4 kv = *(const float4*)&g_k[((size_t)(b*SS + s0 + r))*DD + c];
        *(float4*)&ks[r][c] = kv;
    }
    __syncthreads();

    {
        int r = tid & 127, h = tid >> 7;
        ULL acc[4] = {0ull,0ull,0ull,0ull};
        #pragma unroll
        for (int i = 0; i < 16; i++) {
            ulonglong2 kv = *(const ulonglong2*)&ks[r][i*4];
            #pragma unroll
            for (int sg = 0; sg < 4; sg++) {
                ulonglong2 qp = *(const ulonglong2*)&qs[h*4 + sg][i*4];
                fma2(acc[sg], qp.x, kv.x);
                fma2(acc[sg], qp.y, kv.y);
            }
        }
        int mk = mask[b*SS + s0 + r];
        #pragma unroll
        for (int sg = 0; sg < 4; sg++) {
            float2 t = upk2(acc[sg]);
            float sc = (t.x + t.y)*0.125f;
            if (mk == 0) sc = -3.402823466e38f;
            ps[h*4 + sg][r] = sc;
            if (last) attn[((size_t)(b*KK + h*4 + sg))*SS + s0 + r] = sc;
        }
    }
    __syncthreads();

    {
        float m = -FLT_MAX;
        #pragma unroll
        for (int j = 0; j < CS/32; j++) m = fmaxf(m, ps[w][lane + 32*j]);
        #pragma unroll
        for (int o = 16; o; o >>= 1) m = fmaxf(m, __shfl_xor_sync(0xffffffffu, m, o));
        float l = 0.f;
        #pragma unroll
        for (int j = 0; j < CS/32; j++) {
            float p = expf(ps[w][lane + 32*j] - m);
            psd[lane + 32*j][w] = make_float2(p, p);
            l += p;
        }
        #pragma unroll
        for (int o = 16; o; o >>= 1) l += __shfl_xor_sync(0xffffffffu, l, o);
        if (lane == 0) {
            g_cst[((ch*BB + b)*KK + w)*2]     = m;
            g_cst[((ch*BB + b)*KK + w)*2 + 1] = l;
        }
    }
    __syncthreads();

    {
        const float* vp = g_v + ((size_t)(b*SS + s0 + w*16))*DD + 2*lane;
        ULL acc[8];
        #pragma unroll
        for (int sl = 0; sl < 8; sl++) acc[sl] = 0ull;
        #pragma unroll
        for (int s = 0; s < 16; s++) {
            ULL vv = *(const ULL*)(vp + (size_t)s*DD);
            const ulonglong2* pp = (const ulonglong2*)&psd[w*16 + s][0];
            ulonglong2 pA = pp[0], pB = pp[1], pC = pp[2], pD = pp[3];
            fma2(acc[0], pA.x, vv); fma2(acc[1], pA.y, vv);
            fma2(acc[2], pB.x, vv); fma2(acc[3], pB.y, vv);
            fma2(acc[4], pC.x, vv); fma2(acc[5], pC.y, vv);
            fma2(acc[6], pD.x, vv); fma2(acc[7], pD.y, vv);
        }
        float* pt = &ks[0][0];
        #pragma unroll
        for (int sl = 0; sl < 8; sl++)
            *(float2*)&pt[(w*8 + sl)*64 + 2*lane] = upk2(acc[sl]);
    }
    __syncthreads();

    {
        int sl = tid >> 5, dp = lane;
        const float* pt = &ks[0][0];
        float sx = 0.f, sy = 0.f;
        #pragma unroll
        for (int ww = 0; ww < 8; ww++) {
            float2 p = *(const float2*)&pt[(ww*8 + sl)*64 + 2*dp];
            sx += p.x; sy += p.y;
        }
        *(float2*)&g_updp[((size_t)(ch*BB + b)*KK + sl)*DD + 2*dp] = make_float2(sx, sy);
    }
}

// ---------------- GRU cell + fused next-iteration q projection ----------------
__global__ __launch_bounds__(192) void k_gru(const float* __restrict__ W_ih,
                                             const float* __restrict__ W_hh,
                                             const float* __restrict__ b_ih,
                                             const float* __restrict__ b_hh,
                                             const float* __restrict__ Wq,
                                             const float* __restrict__ lng,
                                             const float* __restrict__ lnb,
                                             int do_q) {
    __shared__ float su[64], sh[64], gx[192], gh[192], red[2];
    int row = blockIdx.x, tid = threadIdx.x;   // row = b*KK + slot
    int lane = tid & 31, w = tid >> 5;
    if (tid < 64) {
        float m = -FLT_MAX;
        #pragma unroll
        for (int ch = 0; ch < NCH; ch++)
            m = fmaxf(m, g_cst[(ch*BB*KK + row)*2]);
        float l = 0.f, U = 0.f;
        #pragma unroll
        for (int ch = 0; ch < NCH; ch++) {
            float wgt = expf(g_cst[(ch*BB*KK + row)*2] - m);
            l += g_cst[(ch*BB*KK + row)*2 + 1] * wgt;
            U += g_updp[((size_t)ch*BB*KK + row)*DD + tid] * wgt;
        }
        su[tid] = U / l;
        sh[tid] = g_slots[row*DD + tid];
        if (tid == 0) { g_stats[row*2] = m; g_stats[row*2+1] = 1.f/l; }
    }
    __syncthreads();
    float ax = b_ih[tid], ah = b_hh[tid];
    #pragma unroll 8
    for (int j = 0; j < 64; j++) {
        ax += su[j]*W_ih[j*192 + tid];
        ah += sh[j]*W_hh[j*192 + tid];
    }
    gx[tid] = ax; gh[tid] = ah;
    __syncthreads();
    float ns = 0.f;
    if (tid < 64) {
        float r = 1.f/(1.f + expf(-(gx[tid]      + gh[tid])));
        float z = 1.f/(1.f + expf(-(gx[tid+64]   + gh[tid+64])));
        float n = tanhf(gx[tid+128] + r*gh[tid+128]);
        ns = (1.f - z)*n + z*sh[tid];
        g_slots[row*DD + tid] = ns;
    }
    if (!do_q) return;
    __syncthreads();
    // ---- fused q projection for the NEXT iteration ----
    if (tid < 64) {
        float s = ns;
        #pragma unroll
        for (int o = 16; o; o >>= 1) s += __shfl_xor_sync(0xffffffffu, s, o);
        if (lane == 0) red[w] = s;
    }
    __syncthreads();
    float m_ = (red[0] + red[1]) * (1.f/DD);
    float df = ns - m_;
    __syncthreads();
    if (tid < 64) {
        float q2 = df*df;
        #pragma unroll
        for (int o = 16; o; o >>= 1) q2 += __shfl_xor_sync(0xffffffffu, q2, o);
        if (lane == 0) red[w] = q2;
    }
    __syncthreads();
    if (tid < 64) {
        float var = (red[0] + red[1]) * (1.f/DD);
        float rs = rsqrtf(var + EPSN);
        sh[tid] = df*rs*lng[tid] + lnb[tid];
    }
    __syncthreads();
    if (tid < 64) {
        float acc = 0.f;
        #pragma unroll 8
        for (int j = 0; j < DD; j++) acc += sh[j]*Wq[j*DD + tid];
        g_q[row*DD + tid] = acc;
    }
}

// ---------------- merged finale: attn normalize + slots + validity ----------------
__global__ __launch_bounds__(256) void k_fin(const float* __restrict__ Wval,
                                             const float* __restrict__ bval,
                                             float* __restrict__ out,
                                             float* __restrict__ attn) {
    int row = blockIdx.x, tid = threadIdx.x;
    __shared__ float red[2];
    // normalize attn row in place
    float m  = g_stats[row*2];
    float rl = g_stats[row*2 + 1];
    float* a = attn + (size_t)row*SS;
    #pragma unroll 4
    for (int i = tid; i < SS; i += 256)
        a[i] = expf(a[i] - m) * rl;
    // slots + validity (first 64 threads)
    if (tid < 64) {
        float s = g_slots[row*DD + tid];
        out[row*DD + tid] = s;
        float p = s*Wval[tid];
        int lane = tid & 31, w = tid >> 5;
        #pragma unroll
        for (int o = 16; o; o >>= 1) p += __shfl_xor_sync(0xffffffffu, p, o);
        if (lane == 0) red[w] = p;
    }
    __syncthreads();
    if (tid == 0) {
        float v = red[0] + red[1] + bval[0];
        out[(size_t)BB*KK*DD + (size_t)BB*KK*SS + row] = (v > 0.f) ? 1.f : 0.f;
    }
}

// ---------------- launch ----------------
extern "C" void kernel_launch(void* const* d_in, const int* in_sizes, int n_in,
                              void* d_out, int out_size) {
    const float* inputs   = (const float*)d_in[0];
    const int*   mask     = (const int*)  d_in[1];
    const float* slot_emb = (const float*)d_in[2];
    const float* Wq       = (const float*)d_in[3];
    const float* Wk       = (const float*)d_in[4];
    const float* Wv       = (const float*)d_in[5];
    const float* W_ih     = (const float*)d_in[6];
    const float* W_hh     = (const float*)d_in[7];
    const float* b_ih     = (const float*)d_in[8];
    const float* b_hh     = (const float*)d_in[9];
    const float* ln_in_g  = (const float*)d_in[10];
    const float* ln_in_b  = (const float*)d_in[11];
    const float* ln_s_g   = (const float*)d_in[12];
    const float* ln_s_b   = (const float*)d_in[13];
    const float* Wval     = (const float*)d_in[14];
    const float* bval     = (const float*)d_in[15];
    float* out  = (float*)d_out;
    float* attn = out + BB*KK*DD;   // attn region of d_out doubles as raw-score scratch

    k_init<<<64, 256>>>(slot_emb, Wk, Wv, ln_in_b);
    k_wsplit<<<128, 256>>>(Wk, Wv, ln_in_g);
    k_proj<<<NROW/128, 256>>>(inputs);
    k_q<<<BB*KK, 64>>>(Wq, ln_s_g, ln_s_b);
    for (int it = 0; it < 3; it++) {
        k_iter<<<dim3(NCH, BB), 256>>>(mask, attn, (it == 2) ? 1 : 0);
        k_gru<<<BB*KK, 192>>>(W_ih, W_hh, b_ih, b_hh, Wq, ln_s_g, ln_s_b,
                              (it < 2) ? 1 : 0);
    }
    k_fin<<<BB*KK, 256>>>(Wval, bval, out, attn);
}